// round 17
// baseline (speedup 1.0000x reference)
#include <cuda_runtime.h>
#include <cstdint>

// ---------------------------------------------------------------------------
// SimplifiedHAttention — closed form + XLA-tree Z (R7), GEMMs via int8 IMMA
// m16n8k32 fixed-point emulation (R17):
//   row-scaled a = qa*(128*ah + al), col(W-row)-scaled w = qw*(128*wh + wl)
//   A@W ~= qa*qw*(16384*P[ah,wh] + 128*(P[ah,wl]+P[al,wh]))   (al*wl dropped)
// 3 products at k32 = HALF the mma instructions of bf16 split-3 (R16, whose
// GEMM time proved ∝ instruction count across R8/R13/R14/R16).
// Non-GEMM chain = R16 (passed), with scan_combine emitting f32 att and a
// per-row quant kernel feeding GEMM2.
// ---------------------------------------------------------------------------

#define B_ 2
#define S_ 2048
#define E_ 1024
#define H_ 16
#define TS2 32
#define NT2 (S_ / TS2)      // 64
#define M_ (B_ * S_)        // 4096 GEMM rows
#define GK E_               // 1024 GEMM K (bytes per int8 row)

__device__ float g_vm [(size_t)B_ * S_ * E_];
__device__ float g_att[(size_t)B_ * S_ * E_];
__device__ float g_tsum [(size_t)B_ * NT2 * E_];
__device__ float g_tofff[(size_t)B_ * NT2 * E_];
__device__ float g_toffb[(size_t)B_ * NT2 * E_];
__device__ float4 g_wts[(size_t)B_ * H_ * S_];
// int8 planes + per-row scales
__device__ int8_t g_xqh[(size_t)M_ * E_];
__device__ int8_t g_xql[(size_t)M_ * E_];
__device__ int8_t g_aqh[(size_t)M_ * E_];
__device__ int8_t g_aql[(size_t)M_ * E_];
__device__ int8_t g_wvqh[(size_t)E_ * E_];
__device__ int8_t g_wvql[(size_t)E_ * E_];
__device__ int8_t g_woqh[(size_t)E_ * E_];
__device__ int8_t g_woql[(size_t)E_ * E_];
__device__ float g_qx [M_];
__device__ float g_qa [M_];
__device__ float g_qwv[E_];
__device__ float g_qwo[E_];

// ---------------------------------------------------------------------------
// Per-row quantization: row scale m = max|v|, ia = rn(v*16256/m) in [-16256,
// 16256]; ah = (ia+64)>>7 (int8), al = ia - 128*ah (in [-64,64)).
// One block (256 thr) per 1024-element row.
// ---------------------------------------------------------------------------
__global__ __launch_bounds__(256)
void quant_rows_kernel(const float* __restrict__ src,
                       int8_t* __restrict__ qh, int8_t* __restrict__ ql,
                       float* __restrict__ qs)
{
    __shared__ float red[8];
    int row = blockIdx.x;
    int tid = threadIdx.x;
    const float* s = src + (size_t)row * E_;

    float4 v = ((const float4*)s)[tid];
    float m = fmaxf(fmaxf(fabsf(v.x), fabsf(v.y)), fmaxf(fabsf(v.z), fabsf(v.w)));
    #pragma unroll
    for (int o = 16; o > 0; o >>= 1)
        m = fmaxf(m, __shfl_down_sync(0xffffffffu, m, o));
    if ((tid & 31) == 0) red[tid >> 5] = m;
    __syncthreads();
    if (tid < 8) {
        float t = red[tid];
        #pragma unroll
        for (int o = 4; o > 0; o >>= 1)
            t = fmaxf(t, __shfl_down_sync(0xffu, t, o));
        if (tid == 0) red[0] = fmaxf(t, 1e-20f);
    }
    __syncthreads();
    m = red[0];
    float inv = 16256.0f / m;
    if (tid == 0) qs[row] = m * (1.0f / 16256.0f);

    int ia0 = __float2int_rn(v.x * inv);
    int ia1 = __float2int_rn(v.y * inv);
    int ia2 = __float2int_rn(v.z * inv);
    int ia3 = __float2int_rn(v.w * inv);
    ia0 = max(min(ia0, 16256), -16256);
    ia1 = max(min(ia1, 16256), -16256);
    ia2 = max(min(ia2, 16256), -16256);
    ia3 = max(min(ia3, 16256), -16256);
    int h0 = (ia0 + 64) >> 7, h1 = (ia1 + 64) >> 7;
    int h2 = (ia2 + 64) >> 7, h3 = (ia3 + 64) >> 7;
    char4 ch = make_char4((char)h0, (char)h1, (char)h2, (char)h3);
    char4 cl = make_char4((char)(ia0 - (h0 << 7)), (char)(ia1 - (h1 << 7)),
                          (char)(ia2 - (h2 << 7)), (char)(ia3 - (h3 << 7)));
    ((char4*)(qh + (size_t)row * E_))[tid] = ch;
    ((char4*)(ql + (size_t)row * E_))[tid] = cl;
}

// ---------------------------------------------------------------------------
// GEMM helpers (baseline ISA: cp.async, ldmatrix, mma.sync s8)
// ---------------------------------------------------------------------------
__device__ __forceinline__ void cpasync16(uint32_t saddr, const void* src)
{
    asm volatile("cp.async.cg.shared.global [%0], [%1], 16;" :: "r"(saddr), "l"(src));
}

__device__ __forceinline__ void ldsm_x4(uint32_t* r, uint32_t saddr)
{
    asm volatile("ldmatrix.sync.aligned.m8n8.x4.shared.b16 {%0,%1,%2,%3}, [%4];"
        : "=r"(r[0]), "=r"(r[1]), "=r"(r[2]), "=r"(r[3]) : "r"(saddr));
}

__device__ __forceinline__ void mma_s8(int* c, const uint32_t* a, const uint32_t* b)
{
    asm volatile(
        "mma.sync.aligned.m16n8k32.row.col.s32.s8.s8.s32 "
        "{%0,%1,%2,%3}, {%4,%5,%6,%7}, {%8,%9}, {%0,%1,%2,%3};\n"
        : "+r"(c[0]), "+r"(c[1]), "+r"(c[2]), "+r"(c[3])
        : "r"(a[0]), "r"(a[1]), "r"(a[2]), "r"(a[3]), "r"(b[0]), "r"(b[1]));
}

// Stage: BK=64 int8. Rows (pitch QP=80B; 64B data + 16 pad, ldmatrix
// conflict-free: r*80 mod 128 all-distinct 16B offsets):
//   [0,128) Ah  [128,256) Al  [256,384) Wh  [384,512) Wl
#define QP 80
#define ROWS_STG 512
#define OFF_AL (128 * QP)
#define OFF_WH (256 * QP)
#define OFF_WL (384 * QP)
#define STAGE_BYTES (ROWS_STG * QP)       // 40960
#define GSMEM_BYTES (2 * STAGE_BYTES)     // 81920

// ---------------------------------------------------------------------------
// int8 fixed-point GEMM: C[m,n] = rowmask(m)*(qa[m]*qw[n]*acc + bias[n])
// 128x128 block, 8 warps (2m x 4n), warp tile 64x32, BK=64, double buffer,
// one __syncthreads per K-iter.
// ---------------------------------------------------------------------------
__global__ __launch_bounds__(256, 1)
void gemm_int8_kernel(const int8_t* __restrict__ Ah, const int8_t* __restrict__ Al,
                      const int8_t* __restrict__ Wh, const int8_t* __restrict__ Wl,
                      const float* __restrict__ qa, const float* __restrict__ qw,
                      const float* __restrict__ bias, const int* __restrict__ mask,
                      float* __restrict__ C)
{
    extern __shared__ int8_t sm[];
    const uint32_t sm32 = (uint32_t)__cvta_generic_to_shared(sm);

    const int tid  = threadIdx.x;
    const int lane = tid & 31;
    const int w    = tid >> 5;
    const int wm   = w >> 2;           // 0..1  (64 rows)
    const int wn   = w & 3;            // 0..3  (32 cols)
    const int row0 = blockIdx.y * 128;
    const int col0 = blockIdx.x * 128;
    const int lr   = lane >> 2;        // 0..7
    const int lq   = (lane & 3) << 1;  // 0,2,4,6

    // ldmatrix lane bases (bytes). amat bit0/bit1 semantics identical to the
    // R13-validated bf16 mapping (16B k-chunks; A: bit0=row-half, bit1=k16;
    // B: bit0=k16, bit1=n-8-tile).
    const int amat = lane >> 3, arow = lane & 7;
    const uint32_t aoff = (uint32_t)((wm * 64 + (amat & 1) * 8 + arow) * QP
                                     + (amat >> 1) * 16);
    const uint32_t boff = (uint32_t)((wn * 32 + (amat >> 1) * 8 + arow) * QP
                                     + (amat & 1) * 16);

    int acc0[4][4][4], acc1[4][4][4];
    #pragma unroll
    for (int ms = 0; ms < 4; ms++)
        #pragma unroll
        for (int ns = 0; ns < 4; ns++)
            #pragma unroll
            for (int t = 0; t < 4; t++) { acc0[ms][ns][t] = 0; acc1[ms][ns][t] = 0; }

    // 8 cp.async per thread per stage: 512 rows x 4 16B-chunks / 256 thr.
    #define COPY_STAGE(stg, kbase) do {                                        \
        uint32_t sb = sm32 + (uint32_t)((stg) * STAGE_BYTES);                  \
        _Pragma("unroll")                                                      \
        for (int i = 0; i < 8; i++) {                                          \
            int f  = tid + i * 256;                                            \
            int r  = f >> 2;                                                   \
            int ck = (f & 3) << 4;                                             \
            const int8_t* g; int grow;                                        \
            if (r < 128)      { g = Ah; grow = row0 + r; }                     \
            else if (r < 256) { g = Al; grow = row0 + r - 128; }               \
            else if (r < 384) { g = Wh; grow = col0 + r - 256; }               \
            else              { g = Wl; grow = col0 + r - 384; }               \
            cpasync16(sb + (uint32_t)(r * QP + ck),                            \
                      g + (size_t)grow * GK + (kbase) + ck);                   \
        }                                                                      \
    } while (0)

    COPY_STAGE(0, 0);
    asm volatile("cp.async.commit_group;");

    const int NITER = GK / 64;     // 16
    for (int it = 0; it < NITER; it++) {
        asm volatile("cp.async.wait_group 0;");
        __syncthreads();
        if (it + 1 < NITER) COPY_STAGE((it + 1) & 1, (it + 1) * 64);
        asm volatile("cp.async.commit_group;");

        const uint32_t sb = sm32 + (uint32_t)((it & 1) * STAGE_BYTES);
        #pragma unroll
        for (int kh = 0; kh < 2; kh++) {           // two k32 halves
            const uint32_t kb = (uint32_t)(kh * 32);
            uint32_t bh[2][4], bl[2][4];
            #pragma unroll
            for (int p = 0; p < 2; p++) {          // 2 x (2 n-tiles)
                uint32_t ba = sb + boff + (uint32_t)(p * 16 * QP) + kb;
                ldsm_x4(bh[p], ba + (uint32_t)OFF_WH);
                ldsm_x4(bl[p], ba + (uint32_t)OFF_WL);
            }
            #pragma unroll
            for (int ms = 0; ms < 4; ms++) {
                uint32_t aa = sb + aoff + (uint32_t)(ms * 16 * QP) + kb;
                uint32_t ah[4], al[4];
                ldsm_x4(ah, aa);
                ldsm_x4(al, aa + (uint32_t)OFF_AL);
                #pragma unroll
                for (int ns = 0; ns < 4; ns++) {
                    const uint32_t* bhp = &bh[ns >> 1][(ns & 1) * 2];
                    const uint32_t* blp = &bl[ns >> 1][(ns & 1) * 2];
                    mma_s8(acc0[ms][ns], ah, bhp);   // 16384x
                    mma_s8(acc1[ms][ns], ah, blp);   // 128x
                    mma_s8(acc1[ms][ns], al, bhp);   // 128x (shared acc)
                }
            }
        }
    }

    // Epilogue: out = mask * (qa*qw*(16384*acc0 + 128*acc1) + bias)
    #pragma unroll
    for (int ms = 0; ms < 4; ms++) {
        int r = row0 + wm * 64 + ms * 16 + lr;
        float qa0 = qa[r], qa1 = qa[r + 8];
        float m0 = mask ? (float)mask[r]     : 1.0f;
        float m1 = mask ? (float)mask[r + 8] : 1.0f;
        #pragma unroll
        for (int ns = 0; ns < 4; ns++) {
            int c = col0 + wn * 32 + ns * 8 + lq;
            float s00 = qa0 * qw[c], s01 = qa0 * qw[c + 1];
            float s10 = qa1 * qw[c], s11 = qa1 * qw[c + 1];
            float b0 = bias[c], b1 = bias[c + 1];
            float v0 = fmaf(16384.0f, (float)acc0[ms][ns][0],
                            128.0f * (float)acc1[ms][ns][0]);
            float v1 = fmaf(16384.0f, (float)acc0[ms][ns][1],
                            128.0f * (float)acc1[ms][ns][1]);
            float v2 = fmaf(16384.0f, (float)acc0[ms][ns][2],
                            128.0f * (float)acc1[ms][ns][2]);
            float v3 = fmaf(16384.0f, (float)acc0[ms][ns][3],
                            128.0f * (float)acc1[ms][ns][3]);
            float2 o0 = make_float2(m0 * (v0 * s00 + b0), m0 * (v1 * s01 + b1));
            float2 o1 = make_float2(m1 * (v2 * s10 + b0), m1 * (v3 * s11 + b1));
            *(float2*)(C + (size_t)r * E_ + c)       = o0;
            *(float2*)(C + (size_t)(r + 8) * E_ + c) = o1;
        }
    }
}

// ---------------------------------------------------------------------------
// K2a: per-(b,t,e) tile sums of vm along S, TS2=32.
// ---------------------------------------------------------------------------
__global__ __launch_bounds__(256)
void tilesum_kernel(const float* __restrict__ vm, float* __restrict__ tsum)
{
    int e = blockIdx.x * 256 + threadIdx.x;
    int t = blockIdx.y;
    int b = blockIdx.z;
    const float* src = vm + ((size_t)b * S_ + (size_t)t * TS2) * E_ + e;
    float acc = 0.0f;
    #pragma unroll
    for (int s = 0; s < TS2; s++)
        acc += src[(size_t)s * E_];
    tsum[((size_t)b * NT2 + t) * E_ + e] = acc;
}

// ---------------------------------------------------------------------------
// K3: cross-tile fwd(exclusive)/bwd(inclusive-from-t) offsets.
// ---------------------------------------------------------------------------
__global__ __launch_bounds__(256)
void scan_tiles_kernel(const float* __restrict__ tsum,
                       float* __restrict__ toff_f, float* __restrict__ toff_b)
{
    int e = blockIdx.x * 256 + threadIdx.x;
    int b = blockIdx.y;
    float acc = 0.0f;
    #pragma unroll 8
    for (int t = 0; t < NT2; t++) {
        size_t idx = ((size_t)b * NT2 + t) * E_ + e;
        toff_f[idx] = acc;
        acc += tsum[idx];
    }
    acc = 0.0f;
    #pragma unroll 8
    for (int t = NT2 - 1; t >= 0; t--) {
        size_t idx = ((size_t)b * NT2 + t) * E_ + e;
        acc += tsum[idx];
        toff_b[idx] = acc;
    }
}

// ---------------------------------------------------------------------------
// K_w: per-(b,h,i) weights, Z in XLA:GPU row-reduce order (R7-validated —
// do not touch).
// ---------------------------------------------------------------------------
__device__ __forceinline__ float wval(int j, int i, int odd,
                                      float c0, float c1, float c2)
{
    if (j >= i) return c0;
    if (odd && j == i - 1) return c1;
    return c2;
}

__global__ __launch_bounds__(256)
void weights_kernel(const float* __restrict__ hier, float4* __restrict__ wts)
{
    int i = blockIdx.x * 256 + threadIdx.x;
    int h = blockIdx.y;
    int b = blockIdx.z;
    const float* hp = hier + ((size_t)b * H_ + h) * 3;
    float c0 = hp[0];
    float c1 = __fmul_rn(0.5f,  hp[1]);
    float c2 = __fmul_rn(0.25f, hp[2]);
    int odd = i & 1;

    float r[32];
    #pragma unroll 1
    for (int w = 0; w < 32; w++) {
        int jlo = w << 6;
        int jhi = jlo + 63;
        if (jlo >= i) {
            r[w] = __fmul_rn(64.0f, c0);
        } else if (jhi < i && !(odd && (i - 1) <= jhi)) {
            r[w] = __fmul_rn(64.0f, c2);
        } else {
            float p[32];
            #pragma unroll
            for (int t = 0; t < 32; t++) {
                int j = jlo + 2 * t;
                p[t] = __fadd_rn(wval(j, i, odd, c0, c1, c2),
                                 wval(j + 1, i, odd, c0, c1, c2));
            }
            #pragma unroll
            for (int s = 16; s > 0; s >>= 1)
                #pragma unroll
                for (int l = 0; l < 16; l++)
                    if (l < s) p[l] = __fadd_rn(p[l], p[l + s]);
            r[w] = p[0];
        }
    }
    #pragma unroll
    for (int s = 16; s > 0; s >>= 1)
        #pragma unroll
        for (int l = 0; l < 16; l++)
            if (l < s) r[l] = __fadd_rn(r[l], r[l + s]);

    float Z = __fadd_rn(r[0], 1e-8f);
    float4 o;
    o.x = __fdiv_rn(c0, Z);
    o.y = __fdiv_rn(c1, Z);
    o.z = __fdiv_rn(c2, Z);
    o.w = 0.0f;
    wts[((size_t)b * H_ + h) * S_ + i] = o;
}

// ---------------------------------------------------------------------------
// K4: fused local-scan + combine, TS2=32 per block-tile -> att (f32).
// ---------------------------------------------------------------------------
__global__ __launch_bounds__(256)
void scan_combine_kernel(const float* __restrict__ vm,
                         const float* __restrict__ toff_f,
                         const float* __restrict__ toff_b,
                         const float4* __restrict__ wts,
                         float* __restrict__ att)
{
    int e = blockIdx.x * 256 + threadIdx.x;
    int t = blockIdx.y;
    int b = blockIdx.z;
    int h = e >> 6;                                  // dh = 64
    size_t tidx = ((size_t)b * NT2 + t) * E_ + e;
    float offf = toff_f[tidx];
    float offb = toff_b[tidx];
    const float4* wp = wts + ((size_t)b * H_ + h) * S_ + (size_t)t * TS2;

    size_t cbase = ((size_t)b * S_ + (size_t)t * TS2) * E_ + e;
    const float* src = vm + cbase;
    float* dst = att + cbase;

    float acc = 0.0f, vprev = 0.0f;
    #pragma unroll
    for (int s = 0; s < TS2; s++) {
        float v = src[(size_t)s * E_];
        float p  = offf + acc;
        float sf = offb - acc;
        float4 ww = wp[s];
        float edge = (s & 1) ? vprev : 0.0f;
        dst[(size_t)s * E_] = ww.x * sf + ww.y * edge + ww.z * (p - edge);
        acc += v;
        vprev = v;
    }
}

// ---------------------------------------------------------------------------
// Launch. Inputs (metadata order):
// 0:x 1:attention_mask 2:level_indices(unused) 3:Wq 4:bq 5:Wk 6:bk
// 7:Wv 8:bv 9:hier 10:Wo 11:bo
// ---------------------------------------------------------------------------
extern "C" void kernel_launch(void* const* d_in, const int* in_sizes, int n_in,
                              void* d_out, int out_size)
{
    const float* x    = (const float*)d_in[0];
    const int*   am   = (const int*)  d_in[1];
    const float* Wv   = (const float*)d_in[7];
    const float* bv   = (const float*)d_in[8];
    const float* hier = (const float*)d_in[9];
    const float* Wo   = (const float*)d_in[10];
    const float* bo   = (const float*)d_in[11];
    float* out = (float*)d_out;

    float *vm, *att, *tsum, *toff_f, *toff_b;
    float4* wts;
    int8_t *xqh, *xql, *aqh, *aql, *wvqh, *wvql, *woqh, *woql;
    float *qx, *qa, *qwv, *qwo;
    cudaGetSymbolAddress((void**)&vm,     g_vm);
    cudaGetSymbolAddress((void**)&att,    g_att);
    cudaGetSymbolAddress((void**)&tsum,   g_tsum);
    cudaGetSymbolAddress((void**)&toff_f, g_tofff);
    cudaGetSymbolAddress((void**)&toff_b, g_toffb);
    cudaGetSymbolAddress((void**)&wts,    g_wts);
    cudaGetSymbolAddress((void**)&xqh,    g_xqh);
    cudaGetSymbolAddress((void**)&xql,    g_xql);
    cudaGetSymbolAddress((void**)&aqh,    g_aqh);
    cudaGetSymbolAddress((void**)&aql,    g_aql);
    cudaGetSymbolAddress((void**)&wvqh,   g_wvqh);
    cudaGetSymbolAddress((void**)&wvql,   g_wvql);
    cudaGetSymbolAddress((void**)&woqh,   g_woqh);
    cudaGetSymbolAddress((void**)&woql,   g_woql);
    cudaGetSymbolAddress((void**)&qx,     g_qx);
    cudaGetSymbolAddress((void**)&qa,     g_qa);
    cudaGetSymbolAddress((void**)&qwv,    g_qwv);
    cudaGetSymbolAddress((void**)&qwo,    g_qwo);

    static int smem_set = 0;
    if (!smem_set) {
        cudaFuncSetAttribute(gemm_int8_kernel,
                             cudaFuncAttributeMaxDynamicSharedMemorySize,
                             GSMEM_BYTES);
        smem_set = 1;
    }

    // Quantize x, Wv, Wo (per-row scale + two int8 planes)
    quant_rows_kernel<<<M_, 256>>>(x,  xqh,  xql,  qx);
    quant_rows_kernel<<<E_, 256>>>(Wv, wvqh, wvql, qwv);
    quant_rows_kernel<<<E_, 256>>>(Wo, woqh, woql, qwo);

    dim3 gemm_grid(E_ / 128, M_ / 128);   // (8, 32) = 256 CTAs

    // K1: vm = mask * (x @ Wv^T + bv)
    gemm_int8_kernel<<<gemm_grid, 256, GSMEM_BYTES>>>(xqh, xql, wvqh, wvql,
                                                      qx, qwv, bv, am, vm);

    // K_w: weights with XLA-tree Z
    weights_kernel<<<dim3(S_ / 256, H_, B_), 256>>>(hier, wts);

    // K2a/K3: tile sums (TS=32) + cross-tile offsets
    tilesum_kernel<<<dim3(E_ / 256, NT2, B_), 256>>>(vm, tsum);
    scan_tiles_kernel<<<dim3(E_ / 256, B_), 256>>>(tsum, toff_f, toff_b);

    // K4: fused scan+combine -> att (f32)
    scan_combine_kernel<<<dim3(E_ / 256, NT2, B_), 256>>>(vm, toff_f, toff_b,
                                                          wts, att);

    // Quantize att rows for GEMM2
    quant_rows_kernel<<<M_, 256>>>(att, aqh, aql, qa);

    // K5: out = att @ Wo^T + bo
    gemm_int8_kernel<<<gemm_grid, 256, GSMEM_BYTES>>>(aqh, aql, woqh, woql,
                                                      qa, qwo, bo, nullptr, out);
}